// round 4
// baseline (speedup 1.0000x reference)
#include <cuda_runtime.h>

// Problem constants (fixed by the dataset)
#define BB 8
#define CI 32
#define CO 64
#define FF 4
#define HH 64
#define WW 64

#define GRID 128   // <= SM count: guaranteed single co-resident wave

// Scratch (allocation-free rule: __device__ globals)
__device__ float g_iv[BB * CI];
__device__ float g_j0[BB * CI];
__device__ float g_j1[BB * CI];
__device__ unsigned g_arrive = 0;   // ticket grid-barrier counter (never reset)

// ---------------------------------------------------------------------------
// Single persistent kernel:
//  Phase 1 (reduce): 256 (b,i) planes over 128 blocks, half-block per plane.
//    Separable uniform grid: vc[h,w,0]=x0+w*dx, vc[h,w,1]=y0+h*dy
//      s  = sum c_h c_w v;  sw = sum c_h c_w w v;  sh = sum c_h c_w h v
//      iv = d2*s;  j0 = d2*(x0*s + dx*sw);  j1 = d2*(y0*s + dy*sh)
//  Grid barrier (ticket-based, reset-free across graph replays).
//  Phase 2 (combine+fill): 512 (b,o) planes over 128 blocks, 4 per block.
//    warp p   (p<4): (s0,s1) = sum_{f,i} Wx[f,o,i,:] * iv[b,i]
//    warp p+4      :  c      = sum_{f,i} Wy[f,o,i,0]*j0 + Wy[f,o,i,1]*j1
//    out[b,o,h,w] = s0*tc_x + s1*tc_y + c   (analytic separable tc)
// ---------------------------------------------------------------------------
__global__ __launch_bounds__(256) void frl_fused(
    const float* __restrict__ v,  const float* __restrict__ vc,
    const float* __restrict__ tc, const float* __restrict__ Wx,
    const float* __restrict__ Wy, float* __restrict__ out)
{
    const int tid = threadIdx.x;
    const int wid = tid >> 5, lid = tid & 31;

    __shared__ float part[3][8];     // phase-1 per-warp partials
    __shared__ float coef[4][3];     // phase-2 (s0, s1, c) per plane

    // ================= Phase 1: weighted plane reductions =================
    {
        const int half = tid >> 7;                  // 0 or 1
        const int t    = tid & 127;
        const int bi   = blockIdx.x * 2 + half;     // 0..255
        const float4* __restrict__ plane =
            reinterpret_cast<const float4*>(v + (size_t)bi * (HH * WW));

        float s = 0.f, sw = 0.f, sh = 0.f;
#pragma unroll
        for (int k = 0; k < 8; ++k) {
            const int q = t + k * 128;              // float4 idx 0..1023
            const float4 tt = plane[q];
            const int h  = q >> 4;
            const int wq = q & 15;
            const float ch = (h == 0 || h == HH - 1) ? 0.5f : 1.0f;
            const float c0 = ch * ((wq == 0)  ? 0.5f : 1.0f);
            const float c3 = ch * ((wq == 15) ? 0.5f : 1.0f);
            const float w0 = (float)(wq * 4);

            const float a0 = c0 * tt.x;
            const float a1 = ch * tt.y;
            const float a2 = ch * tt.z;
            const float a3 = c3 * tt.w;
            const float a  = a0 + a1 + a2 + a3;

            s  += a;
            sh += (float)h * a;
            sw += a0 * w0 + a1 * (w0 + 1.f) + a2 * (w0 + 2.f) + a3 * (w0 + 3.f);
        }
#pragma unroll
        for (int off = 16; off > 0; off >>= 1) {
            s  += __shfl_down_sync(0xffffffffu, s,  off);
            sw += __shfl_down_sync(0xffffffffu, sw, off);
            sh += __shfl_down_sync(0xffffffffu, sh, off);
        }
        if (lid == 0) { part[0][wid] = s; part[1][wid] = sw; part[2][wid] = sh; }
        __syncthreads();

        if (tid == 0 || tid == 128) {
            const int base = half * 4;
            float a = 0.f, b = 0.f, c = 0.f;
#pragma unroll
            for (int i = 0; i < 4; ++i) {
                a += part[0][base + i];
                b += part[1][base + i];
                c += part[2][base + i];
            }
            const float x0 = vc[0];
            const float y0 = vc[1];
            const float dx = vc[2] - vc[0];             // x spacing (ref's dx)
            const float dy = vc[2 * WW + 1] - vc[1];    // y spacing
            const float d2 = dx * dx;                   // ref uses dx for both
            g_iv[bi] = a * d2;
            g_j0[bi] = (x0 * a + dx * b) * d2;
            g_j1[bi] = (y0 * a + dy * c) * d2;
        }
    }

    // ================= Grid barrier (ticket-based, reset-free) =============
    __syncthreads();
    if (tid == 0) {
        __threadfence();                                    // release writes
        const unsigned ticket = atomicAdd(&g_arrive, 1u) + 1u;
        const unsigned target = ((ticket + GRID - 1u) / GRID) * GRID;
        while (atomicAdd(&g_arrive, 0u) < target) { }
        __threadfence();                                    // acquire
    }
    __syncthreads();

    // ================= Phase 2: combine + broadcast fill ===================
    {
        const int plbase = blockIdx.x * 4;                  // 4 planes per block
        // warps 0-3: Wx side for plane (wid); warps 4-7: Wy side for plane (wid-4)
        const int p  = wid & 3;
        const int pl = plbase + p;
        const int b  = pl >> 6;
        const int oo = pl & 63;
        const int i  = lid;

        if (wid < 4) {
            const float ivv = g_iv[b * CI + i];
            float a0 = 0.f, a1 = 0.f;
#pragma unroll
            for (int f = 0; f < FF; ++f) {
                const float2 wx = reinterpret_cast<const float2*>(Wx)
                                      [f * (CO * CI) + oo * CI + i];
                a0 += wx.x * ivv;
                a1 += wx.y * ivv;
            }
#pragma unroll
            for (int off = 16; off > 0; off >>= 1) {
                a0 += __shfl_down_sync(0xffffffffu, a0, off);
                a1 += __shfl_down_sync(0xffffffffu, a1, off);
            }
            if (lid == 0) { coef[p][0] = a0; coef[p][1] = a1; }
        } else {
            const float j0v = g_j0[b * CI + i];
            const float j1v = g_j1[b * CI + i];
            float ac = 0.f;
#pragma unroll
            for (int f = 0; f < FF; ++f) {
                const float2 wy = reinterpret_cast<const float2*>(Wy)
                                      [f * (CO * CI) + oo * CI + i];
                ac += wy.x * j0v + wy.y * j1v;
            }
#pragma unroll
            for (int off = 16; off > 0; off >>= 1)
                ac += __shfl_down_sync(0xffffffffu, ac, off);
            if (lid == 0) coef[p][2] = ac;
        }
        __syncthreads();

        const float tx0 = tc[0];
        const float ty0 = tc[1];
        const float dtx = tc[2] - tc[0];
        const float dty = tc[2 * WW + 1] - tc[1];

#pragma unroll
        for (int pp = 0; pp < 4; ++pp) {
            const float s0 = coef[pp][0];
            const float s1 = coef[pp][1];
            const float c  = coef[pp][2];
            const float s0dx = s0 * dtx;
            float4* __restrict__ out4 =
                reinterpret_cast<float4*>(out) + (size_t)(plbase + pp) * 1024;
#pragma unroll
            for (int k = 0; k < 4; ++k) {
                const int q  = tid + k * 256;       // float4 idx 0..1023
                const int h  = q >> 4;
                const int wq = q & 15;
                const float ybase = fmaf(s1, fmaf((float)h, dty, ty0), c);
                const float xv = fmaf(s0, fmaf((float)(wq * 4), dtx, tx0), ybase);
                float4 r;
                r.x = xv;
                r.y = xv + s0dx;
                r.z = xv + 2.0f * s0dx;
                r.w = xv + 3.0f * s0dx;
                out4[q] = r;
            }
        }
    }
}

extern "C" void kernel_launch(void* const* d_in, const int* in_sizes, int n_in,
                              void* d_out, int out_size)
{
    const float* v   = (const float*)d_in[0];   // [B,CI,H,W]
    const float* vc  = (const float*)d_in[1];   // [H,W,2]
    const float* tc  = (const float*)d_in[2];   // [H,W,2]
    const float* Wx  = (const float*)d_in[3];   // [F,CO,CI,2]
    const float* Wy  = (const float*)d_in[4];   // [F,CO,CI,2]
    float* out = (float*)d_out;                  // [B,CO,H,W]

    (void)in_sizes; (void)n_in; (void)out_size;

    frl_fused<<<GRID, 256>>>(v, vc, tc, Wx, Wy, out);
}

// round 5
// speedup vs baseline: 1.0406x; 1.0406x over previous
#include <cuda_runtime.h>

// Problem constants (fixed by the dataset)
#define BB 8
#define CI 32
#define CO 64
#define FF 4
#define HH 64
#define WW 64

#define GRID 256   // all co-resident (<= 2 CTAs/SM on 148 SMs): grid barrier safe

// Scratch (allocation-free rule: __device__ globals)
__device__ float g_iv[BB * CI];
__device__ float g_j0[BB * CI];
__device__ float g_j1[BB * CI];
__device__ unsigned g_arrive = 0;   // monotonic ticket counter (never reset)

// ---------------------------------------------------------------------------
// Single persistent kernel, 256 blocks x 256 threads.
//  Phase 1: one (b,i) plane per block. Separable uniform grid:
//    s  = sum c_h c_w v;  sw = sum c_h c_w w v;  sh = sum c_h c_w h v
//    iv = d2*s;  j0 = d2*(x0*s + dx*sw);  j1 = d2*(y0*s + dy*sh)
//  Pre-barrier: each warp issues its phase-2 Wx/Wy/tc loads (independent of
//    phase 1) so their latency is hidden behind the barrier drain.
//  Grid barrier: one atomicAdd arrival per block; pollers use plain volatile
//    loads (no RMW serialization). Monotonic ticket -> replay-safe.
//  Phase 2: warp w handles plane pl = blockIdx.x*2 + (w>=4); all 4 warps of a
//    plane redundantly compute (s0,s1,c) via xor-butterfly (no smem/sync),
//    then stream 8 coalesced float4 stores each.
// ---------------------------------------------------------------------------
__global__ __launch_bounds__(256) void frl_fused(
    const float* __restrict__ v,  const float* __restrict__ vc,
    const float* __restrict__ tc, const float* __restrict__ Wx,
    const float* __restrict__ Wy, float* __restrict__ out)
{
    const int tid = threadIdx.x;
    const int wid = tid >> 5, lid = tid & 31;

    __shared__ float part[3][8];

    // ---- Phase-2 operand prefetch (independent of phase 1) ----
    const int pl = blockIdx.x * 2 + (wid >> 2);   // plane 0..511
    const int b  = pl >> 6;
    const int oo = pl & 63;
    float2 wxv[FF], wyv[FF];
#pragma unroll
    for (int f = 0; f < FF; ++f) {
        const int w2idx = f * (CO * CI) + oo * CI + lid;
        wxv[f] = reinterpret_cast<const float2*>(Wx)[w2idx];
        wyv[f] = reinterpret_cast<const float2*>(Wy)[w2idx];
    }
    const float tx0 = tc[0];
    const float ty0 = tc[1];
    const float dtx = tc[2] - tc[0];
    const float dty = tc[2 * WW + 1] - tc[1];

    // ================= Phase 1: weighted plane reduction ===================
    {
        const int bi = blockIdx.x;                  // (b,i) plane 0..255
        const float4* __restrict__ plane =
            reinterpret_cast<const float4*>(v + (size_t)bi * (HH * WW));

        float s = 0.f, sw = 0.f, sh = 0.f;
#pragma unroll
        for (int k = 0; k < 4; ++k) {
            const int q = tid + k * 256;            // float4 idx 0..1023
            const float4 tt = plane[q];
            const int h  = q >> 4;
            const int wq = q & 15;
            const float ch = (h == 0 || h == HH - 1) ? 0.5f : 1.0f;
            const float c0 = ch * ((wq == 0)  ? 0.5f : 1.0f);
            const float c3 = ch * ((wq == 15) ? 0.5f : 1.0f);
            const float w0 = (float)(wq * 4);

            const float a0 = c0 * tt.x;
            const float a1 = ch * tt.y;
            const float a2 = ch * tt.z;
            const float a3 = c3 * tt.w;
            const float a  = a0 + a1 + a2 + a3;

            s  += a;
            sh += (float)h * a;
            sw += a0 * w0 + a1 * (w0 + 1.f) + a2 * (w0 + 2.f) + a3 * (w0 + 3.f);
        }
#pragma unroll
        for (int off = 16; off > 0; off >>= 1) {
            s  += __shfl_down_sync(0xffffffffu, s,  off);
            sw += __shfl_down_sync(0xffffffffu, sw, off);
            sh += __shfl_down_sync(0xffffffffu, sh, off);
        }
        if (lid == 0) { part[0][wid] = s; part[1][wid] = sw; part[2][wid] = sh; }
        __syncthreads();

        if (tid == 0) {
            float a = 0.f, bb2 = 0.f, cc = 0.f;
#pragma unroll
            for (int i = 0; i < 8; ++i) {
                a += part[0][i]; bb2 += part[1][i]; cc += part[2][i];
            }
            const float x0 = vc[0];
            const float y0 = vc[1];
            const float dx = vc[2] - vc[0];             // x spacing (ref's dx)
            const float dy = vc[2 * WW + 1] - vc[1];    // y spacing
            const float d2 = dx * dx;                   // ref uses dx for both
            g_iv[bi] = a * d2;
            g_j0[bi] = (x0 * a + dx * bb2) * d2;
            g_j1[bi] = (y0 * a + dy * cc) * d2;
        }
    }

    // ================= Grid barrier (ticket, volatile-load poll) ===========
    __syncthreads();
    if (tid == 0) {
        __threadfence();                                    // release g_* writes
        const unsigned ticket = atomicAdd(&g_arrive, 1u) + 1u;
        const unsigned target = ((ticket + GRID - 1u) / GRID) * GRID;
        const volatile unsigned* ctr = (const volatile unsigned*)&g_arrive;
        while (*ctr < target) { }                           // plain LDG poll
        __threadfence();                                    // acquire
    }
    __syncthreads();

    // ================= Phase 2: combine + broadcast fill ===================
    {
        const float ivv = g_iv[b * CI + lid];
        const float j0v = g_j0[b * CI + lid];
        const float j1v = g_j1[b * CI + lid];

        float s0 = 0.f, s1 = 0.f, c = 0.f;
#pragma unroll
        for (int f = 0; f < FF; ++f) {
            s0 += wxv[f].x * ivv;
            s1 += wxv[f].y * ivv;
            c  += wyv[f].x * j0v + wyv[f].y * j1v;
        }
        // butterfly: every lane ends with the full sums
#pragma unroll
        for (int off = 16; off > 0; off >>= 1) {
            s0 += __shfl_xor_sync(0xffffffffu, s0, off);
            s1 += __shfl_xor_sync(0xffffffffu, s1, off);
            c  += __shfl_xor_sync(0xffffffffu, c,  off);
        }

        const float s0dx = s0 * dtx;
        float4* __restrict__ out4 =
            reinterpret_cast<float4*>(out) + (size_t)pl * 1024;
        const int wp = wid & 3;                    // warp-within-plane 0..3

#pragma unroll
        for (int k = 0; k < 8; ++k) {
            const int q  = wp * 256 + k * 32 + lid;   // float4 idx 0..1023
            const int h  = q >> 4;
            const int wq = q & 15;
            const float ybase = fmaf(s1, fmaf((float)h, dty, ty0), c);
            const float xv = fmaf(s0, fmaf((float)(wq * 4), dtx, tx0), ybase);
            float4 r;
            r.x = xv;
            r.y = xv + s0dx;
            r.z = xv + 2.0f * s0dx;
            r.w = xv + 3.0f * s0dx;
            out4[q] = r;
        }
    }
}

extern "C" void kernel_launch(void* const* d_in, const int* in_sizes, int n_in,
                              void* d_out, int out_size)
{
    const float* v   = (const float*)d_in[0];   // [B,CI,H,W]
    const float* vc  = (const float*)d_in[1];   // [H,W,2]
    const float* tc  = (const float*)d_in[2];   // [H,W,2]
    const float* Wx  = (const float*)d_in[3];   // [F,CO,CI,2]
    const float* Wy  = (const float*)d_in[4];   // [F,CO,CI,2]
    float* out = (float*)d_out;                  // [B,CO,H,W]

    (void)in_sizes; (void)n_in; (void)out_size;

    frl_fused<<<GRID, 256>>>(v, vc, tc, Wx, Wy, out);
}